// round 3
// baseline (speedup 1.0000x reference)
#include <cuda_runtime.h>

// Problem constants
#define HD      768
#define SEQ     256
#define BATCH   4
#define ROWS    (BATCH * SEQ)      // 1024
#define NTOT    (3 * HD)           // 2304 : [h | ha | hb]
#define NP      54
#define THRESH  0.5f
#define OUT_ELEMS (BATCH * SEQ * SEQ * NP)   // 14,155,776

typedef unsigned long long u64;

// Scratch (device globals — no allocation allowed)
__device__ float g_hab[ROWS * NTOT];          // 9.44 MB
__device__ int   g_cand[ROWS];

// ---------------------------------------------------------------------------
// packed f32x2 helpers
// ---------------------------------------------------------------------------
__device__ __forceinline__ void fma2(u64& d, u64 a, u64 b) {
    asm("fma.rn.f32x2 %0, %1, %2, %0;" : "+l"(d) : "l"(a), "l"(b));
}
__device__ __forceinline__ void unpack2(float& lo, float& hi, u64 v) {
    asm("mov.b64 {%0, %1}, %2;" : "=f"(lo), "=f"(hi) : "l"(v));
}

// ---------------------------------------------------------------------------
// Kernel 1: fused SGEMM  C[1024, 2304] = [ relu(x@W1s^T+b1s) | x@Wa^T | x@Wb^T ]
// 128x128 tile, BK=16, 256 threads, 8x8 per thread via fma.rn.f32x2.
// A duplicated in smem so LDS.128 yields (a,a) pairs directly.
// ---------------------------------------------------------------------------
#define BM 128
#define BN 128
#define BK 16
#define LDA (2*BM + 4)   // 260 floats per k-row (duplicated A), 16B-aligned rows
#define LDB (BN + 4)     // 132 floats per k-row, 16B-aligned rows

__global__ void __launch_bounds__(256, 1) gemm_kernel(
    const float* __restrict__ X,
    const float* __restrict__ W1s,
    const float* __restrict__ b1s,
    const float* __restrict__ Wp1)
{
    __shared__ float AsD[BK * LDA];   // 16.6 KB
    __shared__ float Bs [BK * LDB];   //  8.4 KB

    const int tid = threadIdx.x;
    const int n0 = blockIdx.x * BN;
    const int m0 = blockIdx.y * BM;

    // weight region select (tiles never straddle 768-boundaries)
    const float* Wsrc;
    int rowstride, coloff, nbase;
    bool do_relu;
    if (n0 < HD)            { Wsrc = W1s; rowstride = HD;     coloff = 0;  nbase = 0;      do_relu = true;  }
    else if (n0 < 2 * HD)   { Wsrc = Wp1; rowstride = 2 * HD; coloff = 0;  nbase = HD;     do_relu = false; }
    else                    { Wsrc = Wp1; rowstride = 2 * HD; coloff = HD; nbase = 2 * HD; do_relu = false; }

    u64 acc[8][4];
    #pragma unroll
    for (int i = 0; i < 8; i++)
        #pragma unroll
        for (int j = 0; j < 4; j++) acc[i][j] = 0ull;

    const int lm0 = tid >> 2;          // 0..63
    const int lkq = (tid & 3) * 4;     // 0,4,8,12
    const int ty  = tid >> 4;          // 0..15
    const int tx  = tid & 15;          // 0..15

    const float* gA0 = &X[(m0 + lm0) * HD + lkq];
    const float* gA1 = &X[(m0 + lm0 + 64) * HD + lkq];
    const float* gB0 = &Wsrc[(n0 + lm0 - nbase) * rowstride + coloff + lkq];
    const float* gB1 = &Wsrc[(n0 + lm0 + 64 - nbase) * rowstride + coloff + lkq];

    // prefetch first tile into registers
    float4 ra0 = *(const float4*)gA0;
    float4 ra1 = *(const float4*)gA1;
    float4 rb0 = *(const float4*)gB0;
    float4 rb1 = *(const float4*)gB1;

    const int NITER = HD / BK;   // 48

    for (int it = 0; it < NITER; it++) {
        // store staged tile: A duplicated, B straight
        {
            float* pa = &AsD[lkq * LDA + 2 * lm0];
            *(float2*)&pa[0 * LDA]       = make_float2(ra0.x, ra0.x);
            *(float2*)&pa[1 * LDA]       = make_float2(ra0.y, ra0.y);
            *(float2*)&pa[2 * LDA]       = make_float2(ra0.z, ra0.z);
            *(float2*)&pa[3 * LDA]       = make_float2(ra0.w, ra0.w);
            *(float2*)&pa[0 * LDA + 128] = make_float2(ra1.x, ra1.x);
            *(float2*)&pa[1 * LDA + 128] = make_float2(ra1.y, ra1.y);
            *(float2*)&pa[2 * LDA + 128] = make_float2(ra1.z, ra1.z);
            *(float2*)&pa[3 * LDA + 128] = make_float2(ra1.w, ra1.w);
            float* pb = &Bs[lkq * LDB + lm0];
            pb[0 * LDB]      = rb0.x;  pb[1 * LDB]      = rb0.y;
            pb[2 * LDB]      = rb0.z;  pb[3 * LDB]      = rb0.w;
            pb[0 * LDB + 64] = rb1.x;  pb[1 * LDB + 64] = rb1.y;
            pb[2 * LDB + 64] = rb1.z;  pb[3 * LDB + 64] = rb1.w;
        }
        __syncthreads();

        // issue next-tile global loads early (consumed at next store)
        if (it + 1 < NITER) {
            int ko = (it + 1) * BK;
            ra0 = *(const float4*)(gA0 + ko);
            ra1 = *(const float4*)(gA1 + ko);
            rb0 = *(const float4*)(gB0 + ko);
            rb1 = *(const float4*)(gB1 + ko);
        }

        #pragma unroll
        for (int k = 0; k < BK; k++) {
            ulonglong2 A0 = *(const ulonglong2*)&AsD[k * LDA + ty * 16 + 0];
            ulonglong2 A1 = *(const ulonglong2*)&AsD[k * LDA + ty * 16 + 4];
            ulonglong2 A2 = *(const ulonglong2*)&AsD[k * LDA + ty * 16 + 8];
            ulonglong2 A3 = *(const ulonglong2*)&AsD[k * LDA + ty * 16 + 12];
            ulonglong2 B0 = *(const ulonglong2*)&Bs[k * LDB + tx * 8];
            ulonglong2 B1 = *(const ulonglong2*)&Bs[k * LDB + tx * 8 + 4];
            u64 ap[8] = {A0.x, A0.y, A1.x, A1.y, A2.x, A2.y, A3.x, A3.y};
            u64 bp[4] = {B0.x, B0.y, B1.x, B1.y};
            #pragma unroll
            for (int i = 0; i < 8; i++)
                #pragma unroll
                for (int j = 0; j < 4; j++)
                    fma2(acc[i][j], ap[i], bp[j]);
        }
        __syncthreads();
    }

    // epilogue
    #pragma unroll
    for (int i = 0; i < 8; i++) {
        int m = m0 + ty * 8 + i;
        #pragma unroll
        for (int j = 0; j < 4; j++) {
            int n = n0 + tx * 8 + 2 * j;
            float lo, hi;
            unpack2(lo, hi, acc[i][j]);
            if (do_relu) {
                lo = fmaxf(lo + b1s[n], 0.f);
                hi = fmaxf(hi + b1s[n + 1], 0.f);
            }
            *(float2*)&g_hab[m * NTOT + n] = make_float2(lo, hi);
        }
    }
}

// ---------------------------------------------------------------------------
// Kernel 2: cand[row] = (h[row] . W2s[0] + b2s[0]) > THRESH   (one warp/row)
// ---------------------------------------------------------------------------
__global__ void cand_kernel(const float* __restrict__ W2s,
                            const float* __restrict__ b2s)
{
    int warp = (blockIdx.x * blockDim.x + threadIdx.x) >> 5;   // 0..1023
    int lane = threadIdx.x & 31;
    float s = 0.f;
    #pragma unroll
    for (int t = 0; t < HD / 32; t++) {
        int k = lane + 32 * t;
        s += g_hab[warp * NTOT + k] * W2s[k];
    }
    #pragma unroll
    for (int o = 16; o > 0; o >>= 1)
        s += __shfl_xor_sync(0xffffffffu, s, o);
    if (lane == 0)
        g_cand[warp] = (s + b2s[0]) > THRESH ? 1 : 0;
}

// ---------------------------------------------------------------------------
// Kernel 3: fused output — one warp per (b,i,j).
//   invalid -> write 54 zeros; valid -> relu(ha_i+hb_j+bp1) @ Wp2^T + bp2
// ---------------------------------------------------------------------------
__global__ void __launch_bounds__(256) out_kernel(
    const float* __restrict__ bp1,
    const float* __restrict__ Wp2,
    const float* __restrict__ bp2,
    float* __restrict__ out)
{
    int w    = (blockIdx.x * blockDim.x + threadIdx.x) >> 5;   // 0..262143
    int lane = threadIdx.x & 31;
    int b = w >> 16;
    int i = (w >> 8) & 255;
    int j = w & 255;
    int rowi = b * SEQ + i;
    int rowj = b * SEQ + j;
    float* o = out + (long long)w * NP;   // w == (rowi*SEQ + j)

    bool valid = (i != j) && g_cand[rowi] && g_cand[rowj];
    if (!valid) {
        o[lane] = 0.f;                    // lanes 0..31
        if (lane < NP - 32) o[lane + 32] = 0.f;
        return;
    }

    // pair hidden in registers (24 values per lane)
    float v[HD / 32];
    #pragma unroll
    for (int t = 0; t < HD / 32; t++) {
        int h = lane + 32 * t;
        v[t] = fmaxf(g_hab[rowi * NTOT + HD + h] +
                     g_hab[rowj * NTOT + 2 * HD + h] + bp1[h], 0.f);
    }
    for (int p = 0; p < NP; p++) {
        float s = 0.f;
        #pragma unroll
        for (int t = 0; t < HD / 32; t++)
            s += v[t] * __ldg(&Wp2[p * HD + lane + 32 * t]);
        #pragma unroll
        for (int off = 16; off > 0; off >>= 1)
            s += __shfl_xor_sync(0xffffffffu, s, off);
        if (lane == 0) o[p] = s + bp2[p];
    }
}

// ---------------------------------------------------------------------------
extern "C" void kernel_launch(void* const* d_in, const int* in_sizes, int n_in,
                              void* d_out, int out_size)
{
    const float* x   = (const float*)d_in[0];   // [4,256,768]
    const float* W1s = (const float*)d_in[1];   // [768,768]
    const float* b1s = (const float*)d_in[2];   // [768]
    const float* W2s = (const float*)d_in[3];   // [2,768]
    const float* b2s = (const float*)d_in[4];   // [2]
    const float* Wp1 = (const float*)d_in[5];   // [768,1536]
    const float* bp1 = (const float*)d_in[6];   // [768]
    const float* Wp2 = (const float*)d_in[7];   // [54,768]
    const float* bp2 = (const float*)d_in[8];   // [54]
    float* out = (float*)d_out;

    // 1) fused SGEMM: h | ha | hb
    dim3 ggrid(NTOT / BN, ROWS / BM);            // (18, 8)
    gemm_kernel<<<ggrid, 256>>>(x, W1s, b1s, Wp1);

    // 2) candidate mask (one warp per row)
    cand_kernel<<<ROWS / 8, 256>>>(W2s, b2s);

    // 3) fused zero + sparse pair logits (one warp per (b,i,j))
    out_kernel<<<(BATCH * SEQ * SEQ) / 8, 256>>>(bp1, Wp2, bp2, out);
}

// round 4
// speedup vs baseline: 1.1044x; 1.1044x over previous
#include <cuda_runtime.h>

#define HD      768
#define SEQ     256
#define BATCH   4
#define ROWS    (BATCH * SEQ)      // 1024
#define NP      54
#define THRESH  0.5f
#define ROWOUT  (SEQ * NP)         // 13824 floats per (b,i) row

typedef unsigned long long u64;

// Scratch (device globals — no allocation allowed)
__device__ float g_hab[ROWS * 2 * HD];   // [row][ha(768) | hb(768)], only candidate rows filled
__device__ float g_part[12 * ROWS];      // partial span dots per n-tile
__device__ int   g_cand[ROWS];
__device__ int   g_rows[ROWS];
__device__ int   g_nrows;

__device__ __forceinline__ void fma2(u64& d, u64 a, u64 b) {
    asm("fma.rn.f32x2 %0, %1, %2, %0;" : "+l"(d) : "l"(a), "l"(b));
}
__device__ __forceinline__ u64 dup2(float a) {
    u64 r; asm("mov.b64 %0, {%1, %1};" : "=l"(r) : "f"(a)); return r;
}
__device__ __forceinline__ void unpack2(float& lo, float& hi, u64 v) {
    asm("mov.b64 {%0, %1}, %2;" : "=f"(lo), "=f"(hi) : "l"(v));
}

// ---------------------------------------------------------------------------
// GEMM1: for n-tile of 64, compute c = x @ W1s^T, then in epilogue
// reduce  sum_n relu(c + b1s[n]) * W2s[0][n]  ->  g_part[ntile][m]
// BM=128, BN=64, BK=16, 128 threads, 8x8 per thread via fma.rn.f32x2.
// ---------------------------------------------------------------------------
#define BM 128
#define BN 64
#define BK 16
#define LDA 132
#define LDB 68

__global__ void __launch_bounds__(128, 1) gemm1_kernel(
    const float* __restrict__ X,
    const float* __restrict__ W1s,
    const float* __restrict__ b1s,
    const float* __restrict__ W2s)
{
    __shared__ float As[2][BK * LDA];
    __shared__ float Bs[2][BK * LDB];
    __shared__ float sp[BM * 9];

    const int tid = threadIdx.x;
    const int n0 = blockIdx.x * BN;
    const int m0 = blockIdx.y * BM;
    const int ty = tid >> 3;          // 0..15 (m-group)
    const int tx = tid & 7;           // 0..7  (n-group)

    const float* gA = X + (m0 + tid) * HD;                       // row tid of tile
    const float* gB = W1s + (n0 + (tid & 63)) * HD + ((tid >> 6) * 8);
    const int kq = (tid >> 6) * 8;    // 0 or 8
    const int bn = tid & 63;

    u64 acc[8][4];
    #pragma unroll
    for (int i = 0; i < 8; i++)
        #pragma unroll
        for (int j = 0; j < 4; j++) acc[i][j] = 0ull;

    float4 ra[4]; float4 rb0, rb1;

    // prologue: load it=0, store buf0, load it=1
    #pragma unroll
    for (int q = 0; q < 4; q++) ra[q] = *(const float4*)(gA + 4 * q);
    rb0 = *(const float4*)(gB);
    rb1 = *(const float4*)(gB + 4);
    {
        #pragma unroll
        for (int q = 0; q < 4; q++) {
            As[0][(4*q+0)*LDA + tid] = ra[q].x;
            As[0][(4*q+1)*LDA + tid] = ra[q].y;
            As[0][(4*q+2)*LDA + tid] = ra[q].z;
            As[0][(4*q+3)*LDA + tid] = ra[q].w;
        }
        Bs[0][(kq+0)*LDB + bn] = rb0.x;  Bs[0][(kq+1)*LDB + bn] = rb0.y;
        Bs[0][(kq+2)*LDB + bn] = rb0.z;  Bs[0][(kq+3)*LDB + bn] = rb0.w;
        Bs[0][(kq+4)*LDB + bn] = rb1.x;  Bs[0][(kq+5)*LDB + bn] = rb1.y;
        Bs[0][(kq+6)*LDB + bn] = rb1.z;  Bs[0][(kq+7)*LDB + bn] = rb1.w;
    }
    #pragma unroll
    for (int q = 0; q < 4; q++) ra[q] = *(const float4*)(gA + BK + 4 * q);
    rb0 = *(const float4*)(gB + BK);
    rb1 = *(const float4*)(gB + BK + 4);

    const int NITER = HD / BK;   // 48
    for (int it = 0; it < NITER; it++) {
        __syncthreads();
        const int cb = it & 1;

        #pragma unroll
        for (int k = 0; k < BK; k++) {
            const float* arp = &As[cb][k * LDA + ty * 8];
            float4 a0 = *(const float4*)arp;
            float4 a1 = *(const float4*)(arp + 4);
            ulonglong2 b01 = *(const ulonglong2*)&Bs[cb][k * LDB + tx * 8];
            ulonglong2 b23 = *(const ulonglong2*)&Bs[cb][k * LDB + tx * 8 + 4];
            u64 bp[4] = {b01.x, b01.y, b23.x, b23.y};
            float av[8] = {a0.x, a0.y, a0.z, a0.w, a1.x, a1.y, a1.z, a1.w};
            #pragma unroll
            for (int i = 0; i < 8; i++) {
                u64 aa = dup2(av[i]);
                #pragma unroll
                for (int j = 0; j < 4; j++) fma2(acc[i][j], aa, bp[j]);
            }
        }

        if (it + 1 < NITER) {
            const int sb = (it + 1) & 1;
            #pragma unroll
            for (int q = 0; q < 4; q++) {
                As[sb][(4*q+0)*LDA + tid] = ra[q].x;
                As[sb][(4*q+1)*LDA + tid] = ra[q].y;
                As[sb][(4*q+2)*LDA + tid] = ra[q].z;
                As[sb][(4*q+3)*LDA + tid] = ra[q].w;
            }
            Bs[sb][(kq+0)*LDB + bn] = rb0.x;  Bs[sb][(kq+1)*LDB + bn] = rb0.y;
            Bs[sb][(kq+2)*LDB + bn] = rb0.z;  Bs[sb][(kq+3)*LDB + bn] = rb0.w;
            Bs[sb][(kq+4)*LDB + bn] = rb1.x;  Bs[sb][(kq+5)*LDB + bn] = rb1.y;
            Bs[sb][(kq+6)*LDB + bn] = rb1.z;  Bs[sb][(kq+7)*LDB + bn] = rb1.w;
            if (it + 2 < NITER) {
                int ko = (it + 2) * BK;
                #pragma unroll
                for (int q = 0; q < 4; q++) ra[q] = *(const float4*)(gA + ko + 4 * q);
                rb0 = *(const float4*)(gB + ko);
                rb1 = *(const float4*)(gB + ko + 4);
            }
        }
    }

    // epilogue: fused relu(c + b1s) * W2s[0], reduce over this tile's 64 n
    float b1v[8], w2v[8];
    #pragma unroll
    for (int jj = 0; jj < 8; jj++) {
        int n = n0 + tx * 8 + jj;
        b1v[jj] = b1s[n];
        w2v[jj] = W2s[n];          // W2s row 0
    }
    __syncthreads();               // done with As/Bs; boundary before sp use
    #pragma unroll
    for (int i = 0; i < 8; i++) {
        float s = 0.f;
        #pragma unroll
        for (int jp = 0; jp < 4; jp++) {
            float lo, hi;
            unpack2(lo, hi, acc[i][jp]);
            s += fmaxf(lo + b1v[2*jp],     0.f) * w2v[2*jp];
            s += fmaxf(hi + b1v[2*jp + 1], 0.f) * w2v[2*jp + 1];
        }
        sp[(ty * 8 + i) * 9 + tx] = s;
    }
    __syncthreads();
    {
        float s = 0.f;
        #pragma unroll
        for (int t = 0; t < 8; t++) s += sp[tid * 9 + t];
        g_part[blockIdx.x * ROWS + m0 + tid] = s;
    }
}

// ---------------------------------------------------------------------------
// cand: span[r] = sum_nt g_part[nt][r] + b2s[0];  cand & compact rows
// single block, 1024 threads (deterministic count; list order irrelevant)
// ---------------------------------------------------------------------------
__global__ void cand_kernel(const float* __restrict__ b2s)
{
    __shared__ int s_cnt;
    int r = threadIdx.x;
    if (r == 0) s_cnt = 0;
    __syncthreads();
    float s = b2s[0];
    #pragma unroll
    for (int nt = 0; nt < 12; nt++) s += g_part[nt * ROWS + r];
    int c = (s > THRESH) ? 1 : 0;
    g_cand[r] = c;
    if (c) {
        int p = atomicAdd(&s_cnt, 1);
        g_rows[p] = r;
    }
    __syncthreads();
    if (r == 0) g_nrows = s_cnt;
}

// ---------------------------------------------------------------------------
// GEMM2: ha/hb for candidate rows only.  work item = (row_slot, 128-col chunk)
// grid-stride over nrows*12 items; 256 threads, warp-per-column dots.
// ---------------------------------------------------------------------------
__global__ void __launch_bounds__(256) gemm2_kernel(
    const float* __restrict__ X,
    const float* __restrict__ Wp1)
{
    __shared__ float xs[HD];
    const int tid  = threadIdx.x;
    const int warp = tid >> 5;
    const int lane = tid & 31;
    const int nrows = g_nrows;
    const int total = nrows * 12;               // 12 chunks of 128 over 1536 cols

    for (int item = blockIdx.x; item < total; item += gridDim.x) {
        int rs = item / 12;
        int chunk = item - rs * 12;
        int row = g_rows[rs];
        __syncthreads();
        for (int k = tid; k < HD; k += 256) xs[k] = X[row * HD + k];
        __syncthreads();
        #pragma unroll 4
        for (int cc = 0; cc < 16; cc++) {
            int c = chunk * 128 + warp * 16 + cc;       // 0..1535
            const float* wrow = (c < HD) ? (Wp1 + (size_t)c * (2 * HD))
                                         : (Wp1 + (size_t)(c - HD) * (2 * HD) + HD);
            float s = 0.f;
            #pragma unroll
            for (int t = 0; t < HD / 32; t++)
                s += xs[lane + 32 * t] * __ldg(&wrow[lane + 32 * t]);
            #pragma unroll
            for (int o = 16; o > 0; o >>= 1)
                s += __shfl_xor_sync(0xffffffffu, s, o);
            if (lane == 0) g_hab[(size_t)row * (2 * HD) + c] = s;
        }
    }
}

// ---------------------------------------------------------------------------
// OUT: one block per (b,i). Non-candidate rows: vectorized zero fill.
// Candidate rows: loop j; zeros for invalid j, warp-dot logits for valid j.
// ---------------------------------------------------------------------------
__global__ void __launch_bounds__(256) out_kernel(
    const float* __restrict__ bp1,
    const float* __restrict__ Wp2,
    const float* __restrict__ bp2,
    float* __restrict__ out)
{
    __shared__ float vsi[HD];
    __shared__ float v[HD];
    __shared__ int   sj[SEQ];

    const int tid  = threadIdx.x;
    const int rowi = blockIdx.x;
    const int b    = rowi >> 8;
    const int i    = rowi & 255;
    float* o = out + (size_t)rowi * ROWOUT;

    if (!g_cand[rowi]) {
        float4* o4 = (float4*)o;
        for (int t = tid; t < ROWOUT / 4; t += 256)
            o4[t] = make_float4(0.f, 0.f, 0.f, 0.f);
        return;
    }

    for (int k = tid; k < HD; k += 256)
        vsi[k] = g_hab[(size_t)rowi * (2 * HD) + k] + bp1[k];
    if (tid < SEQ) sj[tid] = g_cand[(b << 8) | tid];
    __syncthreads();

    const int warp = tid >> 5;
    const int lane = tid & 31;

    for (int j = 0; j < SEQ; j++) {
        bool valid = (j != i) && sj[j];
        if (!valid) {
            if (tid < NP) o[j * NP + tid] = 0.f;
            continue;
        }
        int rowj = (b << 8) | j;
        for (int k = tid; k < HD; k += 256)
            v[k] = fmaxf(vsi[k] + g_hab[(size_t)rowj * (2 * HD) + HD + k], 0.f);
        __syncthreads();
        for (int p = warp; p < NP; p += 8) {
            float s = 0.f;
            #pragma unroll
            for (int t = 0; t < HD / 32; t++)
                s += v[lane + 32 * t] * __ldg(&Wp2[p * HD + lane + 32 * t]);
            #pragma unroll
            for (int off = 16; off > 0; off >>= 1)
                s += __shfl_xor_sync(0xffffffffu, s, off);
            if (lane == 0) o[j * NP + p] = s + bp2[p];
        }
        __syncthreads();
    }
}

// ---------------------------------------------------------------------------
extern "C" void kernel_launch(void* const* d_in, const int* in_sizes, int n_in,
                              void* d_out, int out_size)
{
    const float* x   = (const float*)d_in[0];   // [4,256,768]
    const float* W1s = (const float*)d_in[1];   // [768,768]
    const float* b1s = (const float*)d_in[2];   // [768]
    const float* W2s = (const float*)d_in[3];   // [2,768]
    const float* b2s = (const float*)d_in[4];   // [2]
    const float* Wp1 = (const float*)d_in[5];   // [768,1536]
    const float* bp1 = (const float*)d_in[6];   // [768]
    const float* Wp2 = (const float*)d_in[7];   // [54,768]
    const float* bp2 = (const float*)d_in[8];   // [54]
    float* out = (float*)d_out;

    // 1) x @ W1s^T with fused relu/bias/W2s-dot epilogue -> g_part
    dim3 g1(HD / BN, ROWS / BM);                 // (12, 8) = 96 CTAs
    gemm1_kernel<<<g1, 128>>>(x, W1s, b1s, W2s);

    // 2) candidate mask + row compaction
    cand_kernel<<<1, ROWS>>>(b2s);

    // 3) ha/hb for candidate rows only
    gemm2_kernel<<<256, 256>>>(x, Wp1);

    // 4) zero + sparse pair logits
    out_kernel<<<ROWS, 256>>>(bp1, Wp2, bp2, out);
}

// round 5
// speedup vs baseline: 1.4529x; 1.3155x over previous
#include <cuda_runtime.h>

#define HD      768
#define SEQ     256
#define BATCH   4
#define ROWS    1024
#define NP      54
#define THRESH  0.5f
#define ROWOUT  (SEQ * NP)          // 13824
#define OUT_F4  (ROWS * ROWOUT / 4) // 3,538,944 float4

typedef unsigned long long u64;

// Scratch (device globals — no allocation allowed)
__device__ float g_hab[ROWS * 2 * HD];   // [row][ha(768) | hb(768)], candidate rows only
__device__ float g_part[12 * ROWS];      // partial span dots per n-tile

__device__ __forceinline__ void fma2(u64& d, u64 a, u64 b) {
    asm("fma.rn.f32x2 %0, %1, %2, %0;" : "+l"(d) : "l"(a), "l"(b));
}
__device__ __forceinline__ u64 dup2(float a) {
    u64 r; asm("mov.b64 %0, {%1, %1};" : "=l"(r) : "f"(a)); return r;
}
__device__ __forceinline__ void unpack2(float& lo, float& hi, u64 v) {
    asm("mov.b64 {%0, %1}, %2;" : "=f"(lo), "=f"(hi) : "l"(v));
}

// ---------------------------------------------------------------------------
// GEMM1: c = x @ W1s^T (n-tile of 64); epilogue reduces
//   g_part[ntile][m] = sum_n relu(c + b1s[n]) * W2s[0][n]
// BM=128, BN=64, BK=16, 256 threads, 8m x 4n per thread via fma.rn.f32x2.
// ---------------------------------------------------------------------------
#define BM 128
#define BN 64
#define BK 16
#define LDA 132
#define LDB 68

__global__ void __launch_bounds__(256, 1) gemm1_kernel(
    const float* __restrict__ X,
    const float* __restrict__ W1s,
    const float* __restrict__ b1s,
    const float* __restrict__ W2s)
{
    __shared__ float As[2][BK * LDA];
    __shared__ float Bs[2][BK * LDB];
    __shared__ float sp[BM * 17];

    const int tid = threadIdx.x;
    const int n0 = blockIdx.x * BN;
    const int m0 = blockIdx.y * BM;
    const int ty = tid >> 4;          // 0..15 : rows ty*8..+7
    const int tx = tid & 15;          // 0..15 : cols tx*4..+3

    // loader mapping
    const int am  = tid >> 2;         // 0..63 (A rows am, am+64)
    const int akq = (tid & 3) * 4;    // k quad
    const int bn  = tid & 63;         // B row
    const int bkq = (tid >> 6) * 4;   // k quad (4 groups)

    const float* gA0 = X + (m0 + am) * HD + akq;
    const float* gA1 = gA0 + 64 * HD;
    const float* gB  = W1s + (n0 + bn) * HD + bkq;

    u64 acc[8][2];
    #pragma unroll
    for (int i = 0; i < 8; i++) { acc[i][0] = 0ull; acc[i][1] = 0ull; }

    float4 ra0, ra1, rb;

    // prologue: load tile0, store buf0, load tile1
    ra0 = *(const float4*)gA0;
    ra1 = *(const float4*)gA1;
    rb  = *(const float4*)gB;
    {
        As[0][(akq+0)*LDA + am]      = ra0.x;  As[0][(akq+1)*LDA + am]      = ra0.y;
        As[0][(akq+2)*LDA + am]      = ra0.z;  As[0][(akq+3)*LDA + am]      = ra0.w;
        As[0][(akq+0)*LDA + am + 64] = ra1.x;  As[0][(akq+1)*LDA + am + 64] = ra1.y;
        As[0][(akq+2)*LDA + am + 64] = ra1.z;  As[0][(akq+3)*LDA + am + 64] = ra1.w;
        Bs[0][(bkq+0)*LDB + bn] = rb.x;  Bs[0][(bkq+1)*LDB + bn] = rb.y;
        Bs[0][(bkq+2)*LDB + bn] = rb.z;  Bs[0][(bkq+3)*LDB + bn] = rb.w;
    }
    ra0 = *(const float4*)(gA0 + BK);
    ra1 = *(const float4*)(gA1 + BK);
    rb  = *(const float4*)(gB  + BK);

    const int NITER = HD / BK;   // 48
    for (int it = 0; it < NITER; it++) {
        __syncthreads();
        const int cb = it & 1;

        #pragma unroll
        for (int k = 0; k < BK; k++) {
            const float* arp = &As[cb][k * LDA + ty * 8];
            float4 a0 = *(const float4*)arp;
            float4 a1 = *(const float4*)(arp + 4);
            ulonglong2 bq = *(const ulonglong2*)&Bs[cb][k * LDB + tx * 4];
            float av[8] = {a0.x, a0.y, a0.z, a0.w, a1.x, a1.y, a1.z, a1.w};
            #pragma unroll
            for (int i = 0; i < 8; i++) {
                u64 aa = dup2(av[i]);
                fma2(acc[i][0], aa, bq.x);
                fma2(acc[i][1], aa, bq.y);
            }
        }

        if (it + 1 < NITER) {
            const int sb = (it + 1) & 1;
            As[sb][(akq+0)*LDA + am]      = ra0.x;  As[sb][(akq+1)*LDA + am]      = ra0.y;
            As[sb][(akq+2)*LDA + am]      = ra0.z;  As[sb][(akq+3)*LDA + am]      = ra0.w;
            As[sb][(akq+0)*LDA + am + 64] = ra1.x;  As[sb][(akq+1)*LDA + am + 64] = ra1.y;
            As[sb][(akq+2)*LDA + am + 64] = ra1.z;  As[sb][(akq+3)*LDA + am + 64] = ra1.w;
            Bs[sb][(bkq+0)*LDB + bn] = rb.x;  Bs[sb][(bkq+1)*LDB + bn] = rb.y;
            Bs[sb][(bkq+2)*LDB + bn] = rb.z;  Bs[sb][(bkq+3)*LDB + bn] = rb.w;
            if (it + 2 < NITER) {
                int ko = (it + 2) * BK;
                ra0 = *(const float4*)(gA0 + ko);
                ra1 = *(const float4*)(gA1 + ko);
                rb  = *(const float4*)(gB  + ko);
            }
        }
    }

    // epilogue: fused relu(c + b1s) * W2s[0] reduction over this tile's 64 n
    float b1v[4], w2v[4];
    #pragma unroll
    for (int jj = 0; jj < 4; jj++) {
        int n = n0 + tx * 4 + jj;
        b1v[jj] = b1s[n];
        w2v[jj] = W2s[n];
    }
    __syncthreads();
    #pragma unroll
    for (int i = 0; i < 8; i++) {
        float s = 0.f;
        #pragma unroll
        for (int jp = 0; jp < 2; jp++) {
            float lo, hi;
            unpack2(lo, hi, acc[i][jp]);
            s += fmaxf(lo + b1v[2*jp],     0.f) * w2v[2*jp];
            s += fmaxf(hi + b1v[2*jp + 1], 0.f) * w2v[2*jp + 1];
        }
        sp[(ty * 8 + i) * 17 + tx] = s;
    }
    __syncthreads();
    if (tid < BM) {
        float s = 0.f;
        #pragma unroll
        for (int t = 0; t < 16; t++) s += sp[tid * 17 + t];
        g_part[blockIdx.x * ROWS + m0 + tid] = s;
    }
}

// ---------------------------------------------------------------------------
// MID: zero output + compute ha/hb for candidate rows (cand derived inline)
// grid = 256 blocks x 256 threads
// ---------------------------------------------------------------------------
__global__ void __launch_bounds__(256) mid_kernel(
    const float* __restrict__ X,
    const float* __restrict__ Wp1,
    const float* __restrict__ b2s,
    float* __restrict__ out)
{
    __shared__ int   scand[ROWS];
    __shared__ float xs[HD];

    // phase 0: zero the whole output (coalesced float4 streaming)
    {
        float4* o4 = (float4*)out;
        int base = blockIdx.x * 256 + threadIdx.x;
        #pragma unroll
        for (int t = 0; t < 54; t++)
            o4[base + t * 65536] = make_float4(0.f, 0.f, 0.f, 0.f);
    }

    // phase 1: candidate flags (each block computes full mask from g_part)
    {
        const float b2 = b2s[0];
        for (int r = threadIdx.x; r < ROWS; r += 256) {
            float s = b2;
            #pragma unroll
            for (int nt = 0; nt < 12; nt++) s += g_part[nt * ROWS + r];
            scand[r] = (s > THRESH) ? 1 : 0;
        }
    }
    __syncthreads();

    // phase 2: grid-stride (row, 128-col chunk) items for ha|hb
    const int warp = threadIdx.x >> 5;
    const int lane = threadIdx.x & 31;
    for (int item = blockIdx.x; item < ROWS * 12; item += gridDim.x) {
        int row = item / 12;
        int chunk = item - row * 12;
        if (!scand[row]) continue;                     // block-uniform
        __syncthreads();
        for (int k = threadIdx.x; k < HD; k += 256) xs[k] = X[row * HD + k];
        __syncthreads();
        #pragma unroll 4
        for (int cc = 0; cc < 16; cc++) {
            int c = chunk * 128 + warp * 16 + cc;      // 0..1535
            const float* wrow = (c < HD) ? (Wp1 + (size_t)c * (2 * HD))
                                         : (Wp1 + (size_t)(c - HD) * (2 * HD) + HD);
            float s = 0.f;
            #pragma unroll
            for (int t = 0; t < HD / 32; t++)
                s += xs[lane + 32 * t] * __ldg(&wrow[lane + 32 * t]);
            #pragma unroll
            for (int o = 16; o > 0; o >>= 1)
                s += __shfl_xor_sync(0xffffffffu, s, o);
            if (lane == 0) g_hab[(size_t)row * (2 * HD) + c] = s;
        }
    }
}

// ---------------------------------------------------------------------------
// PAIR: block = (rowi, j-slice of 64). Non-candidate rowi exits immediately.
// Valid (i,j): out[b,i,j,:] = relu(ha_i + hb_j + bp1) @ Wp2^T + bp2
// ---------------------------------------------------------------------------
__global__ void __launch_bounds__(256) pair_kernel(
    const float* __restrict__ b2s,
    const float* __restrict__ bp1,
    const float* __restrict__ Wp2,
    const float* __restrict__ bp2,
    float* __restrict__ out)
{
    const int rowi = blockIdx.x >> 2;
    const int jsl  = blockIdx.x & 3;
    const float b2 = b2s[0];

    // cand(rowi) — all threads compute identically
    {
        float s = b2;
        #pragma unroll
        for (int nt = 0; nt < 12; nt++) s += g_part[nt * ROWS + rowi];
        if (s <= THRESH) return;
    }

    __shared__ float vsi[HD];
    __shared__ float v[HD];
    __shared__ int   sj[64];

    const int b = rowi >> 8;
    const int i = rowi & 255;
    const int tid = threadIdx.x;

    if (tid < 64) {
        int j = jsl * 64 + tid;
        int rowj = (b << 8) | j;
        float s = b2;
        #pragma unroll
        for (int nt = 0; nt < 12; nt++) s += g_part[nt * ROWS + rowj];
        sj[tid] = (j != i) && (s > THRESH);
    }
    for (int k = tid; k < HD; k += 256)
        vsi[k] = g_hab[(size_t)rowi * (2 * HD) + k] + bp1[k];
    __syncthreads();

    const int warp = tid >> 5;
    const int lane = tid & 31;
    float* obase = out + (size_t)rowi * ROWOUT;

    for (int jj = 0; jj < 64; jj++) {
        if (!sj[jj]) continue;
        int j = jsl * 64 + jj;
        int rowj = (b << 8) | j;
        for (int k = tid; k < HD; k += 256)
            v[k] = fmaxf(vsi[k] + g_hab[(size_t)rowj * (2 * HD) + HD + k], 0.f);
        __syncthreads();
        for (int p = warp; p < NP; p += 8) {
            float s = 0.f;
            #pragma unroll
            for (int t = 0; t < HD / 32; t++)
                s += v[lane + 32 * t] * __ldg(&Wp2[p * HD + lane + 32 * t]);
            #pragma unroll
            for (int off = 16; off > 0; off >>= 1)
                s += __shfl_xor_sync(0xffffffffu, s, off);
            if (lane == 0) obase[j * NP + p] = s + bp2[p];
        }
        __syncthreads();
    }
}

// ---------------------------------------------------------------------------
extern "C" void kernel_launch(void* const* d_in, const int* in_sizes, int n_in,
                              void* d_out, int out_size)
{
    const float* x   = (const float*)d_in[0];   // [4,256,768]
    const float* W1s = (const float*)d_in[1];   // [768,768]
    const float* b1s = (const float*)d_in[2];   // [768]
    const float* W2s = (const float*)d_in[3];   // [2,768]
    const float* b2s = (const float*)d_in[4];   // [2]
    const float* Wp1 = (const float*)d_in[5];   // [768,1536]
    const float* bp1 = (const float*)d_in[6];   // [768]
    const float* Wp2 = (const float*)d_in[7];   // [54,768]
    const float* bp2 = (const float*)d_in[8];   // [54]
    float* out = (float*)d_out;

    // 1) x @ W1s^T with fused relu/bias/W2s-dot epilogue -> g_part
    dim3 g1(HD / BN, ROWS / BM);                 // (12, 8) = 96 CTAs
    gemm1_kernel<<<g1, 256>>>(x, W1s, b1s, W2s);

    // 2) zero output + candidate ha/hb
    mid_kernel<<<256, 256>>>(x, Wp1, b2s, out);

    // 3) sparse pair logits
    pair_kernel<<<4096, 256>>>(b2s, bp1, Wp2, bp2, out);
}